// round 2
// baseline (speedup 1.0000x reference)
#include <cuda_runtime.h>
#include <cstdint>

#define NU   100000
#define NPC  20000
#define NURL 50000
#define EUP  250000
#define EUU  500000
#define HD   128

// ---------------- scratch (static __device__, 16B-aligned for float4 access) ----------------
__device__ __align__(16) float g_user[NU*HD];
__device__ __align__(16) float g_pc_a[NPC*HD];
__device__ __align__(16) float g_pc_b[NPC*HD];
__device__ __align__(16) float g_url_a[NURL*HD];
__device__ __align__(16) float g_url_b[NURL*HD];
__device__ __align__(16) float g_mean_pc[NPC*HD];
__device__ __align__(16) float g_mean_url[NURL*HD];
__device__ __align__(16) float g_pcW[NPC*HD];
__device__ __align__(16) float g_urlW[NURL*HD];
__device__ __align__(16) float g_enr[NU*HD];

__device__ int g_cnt_upd[NPC];  __device__ int g_off_upd[NPC+1];  __device__ int g_cur_upd[NPC];  __device__ int g_adj_upd[EUP];
__device__ int g_cnt_uud[NURL]; __device__ int g_off_uud[NURL+1]; __device__ int g_cur_uud[NURL]; __device__ int g_adj_uud[EUU];
__device__ int g_cnt_ups[NU];   __device__ int g_off_ups[NU+1];   __device__ int g_cur_ups[NU];   __device__ int g_adj_ups[EUP];
__device__ int g_cnt_uus[NU];   __device__ int g_off_uus[NU+1];   __device__ int g_cur_uus[NU];   __device__ int g_adj_uus[EUU];

// ---------------- f32x2 packed-FMA helpers ----------------
typedef unsigned long long u64;
__device__ __forceinline__ u64 f2fma(u64 a, u64 b, u64 c) {
    u64 d; asm("fma.rn.f32x2 %0, %1, %2, %3;" : "=l"(d) : "l"(a), "l"(b), "l"(c)); return d;
}
__device__ __forceinline__ u64 f2pack(float x) {
    u64 r; asm("mov.b64 %0, {%1, %1};" : "=l"(r) : "f"(x)); return r;
}
__device__ __forceinline__ void f2unpack(u64 v, float& x, float& y) {
    asm("mov.b64 {%0, %1}, %2;" : "=f"(x), "=f"(y) : "l"(v));
}

// ---------------- CSR build ----------------
__global__ void zero4_kernel(int* a, int na, int* b, int nb, int* c, int nc, int* d, int nd) {
    int i = blockIdx.x * blockDim.x + threadIdx.x;
    if (i < na) a[i] = 0;
    if (i < nb) b[i] = 0;
    if (i < nc) c[i] = 0;
    if (i < nd) d[i] = 0;
}

__global__ void count_kernel(const int* __restrict__ src, const int* __restrict__ dst, int E,
                             int* cntS, int* cntD) {
    int i = blockIdx.x * blockDim.x + threadIdx.x;
    if (i < E) {
        atomicAdd(&cntD[dst[i]], 1);
        atomicAdd(&cntS[src[i]], 1);
    }
}

struct ScanSet { const int* cnt; int* off; int* cur; int n; };

__global__ void scan4_kernel(ScanSet s0, ScanSet s1, ScanSet s2, ScanSet s3) {
    ScanSet s = s0;
    if (blockIdx.x == 1) s = s1; else if (blockIdx.x == 2) s = s2; else if (blockIdx.x == 3) s = s3;
    __shared__ int part[1024];
    int t = threadIdx.x;
    int n = s.n;
    int chunk = (n + 1023) >> 10;
    int beg = t * chunk;
    int end = beg + chunk; if (end > n) end = n; if (beg > n) beg = n;
    int sum = 0;
    #pragma unroll 4
    for (int i = beg; i < end; i++) sum += s.cnt[i];
    part[t] = sum;
    __syncthreads();
    for (int d = 1; d < 1024; d <<= 1) {
        int v = (t >= d) ? part[t - d] : 0;
        __syncthreads();
        part[t] += v;
        __syncthreads();
    }
    int run = (t > 0) ? part[t - 1] : 0;
    for (int i = beg; i < end; i++) {
        s.off[i] = run; s.cur[i] = run;
        run += s.cnt[i];
    }
    if (t == 1023) s.off[n] = part[1023];
}

__global__ void fill_kernel(const int* __restrict__ src, const int* __restrict__ dst, int E,
                            int* curS, int* adjS, int* curD, int* adjD) {
    int i = blockIdx.x * blockDim.x + threadIdx.x;
    if (i < E) {
        int svv = src[i], dvv = dst[i];
        adjD[atomicAdd(&curD[dvv], 1)] = svv;
        adjS[atomicAdd(&curS[svv], 1)] = dvv;
    }
}

// ---------------- small-K input projection: out[N,128] = X[N,Kin] @ W + b ----------------
__global__ void proj_kernel(const float* __restrict__ X, const float* __restrict__ W,
                            const float* __restrict__ b, float* __restrict__ out,
                            int N, int Kin) {
    __shared__ float sW[8 * HD];
    __shared__ float sb[HD];
    __shared__ float sx[32 * 8];
    int tid = threadIdx.x;                 // 128 threads
    for (int i = tid; i < Kin * HD; i += 128) sW[i] = W[i];
    sb[tid] = b[tid];
    int row0 = blockIdx.x * 32;
    int total = 32 * Kin;
    for (int i = tid; i < total; i += 128) {
        int gr = row0 + i / Kin;
        sx[i] = (gr < N) ? X[row0 * Kin + i] : 0.f;
    }
    __syncthreads();
    #pragma unroll 4
    for (int r = 0; r < 32; r++) {
        int gr = row0 + r;
        if (gr >= N) break;
        float acc = sb[tid];
        for (int j = 0; j < Kin; j++) acc = fmaf(sx[r * Kin + j], sW[j * HD + tid], acc);
        out[gr * HD + tid] = acc;
    }
}

// ---------------- gather-based segment mean (CSR by dst) ----------------
__global__ void agg_mean_kernel(const float* __restrict__ feat, const int* __restrict__ off,
                                const int* __restrict__ adj, float* __restrict__ out) {
    int s = blockIdx.x, t = threadIdx.x;   // 128 threads
    int beg = off[s], end = off[s + 1];
    float acc = 0.f;
    int e = beg;
    for (; e + 4 <= end; e += 4) {
        int i0 = adj[e], i1 = adj[e + 1], i2 = adj[e + 2], i3 = adj[e + 3];
        float a0 = feat[i0 * HD + t], a1 = feat[i1 * HD + t];
        float a2 = feat[i2 * HD + t], a3 = feat[i3 * HD + t];
        acc += (a0 + a1) + (a2 + a3);
    }
    for (; e < end; e++) acc += feat[adj[e] * HD + t];
    float inv = (end > beg) ? 1.f / (float)(end - beg) : 0.f;
    out[s * HD + t] = acc * inv;
}

// ---------------- fused GEMM: C = act(A@W1 [+ B@W2] [+bias] [+resid]) , K=128, 128 cols ----------------
#define ASTRIDE 132
__global__ void __launch_bounds__(256) gemm128(
    const float* __restrict__ A, const float* __restrict__ W1,
    const float* __restrict__ B, const float* __restrict__ W2,
    const float* __restrict__ bias, const float* __restrict__ resid,
    float* __restrict__ C, int N, int doRelu)
{
    extern __shared__ float smem[];
    float* As = smem;
    float* Bs = smem + 64 * ASTRIDE;
    const int tid = threadIdx.x;
    const int row0 = blockIdx.x * 64;
    const bool hasB = (B != nullptr);

    // load 64x128 tiles (padded rows -> conflict-free column reads)
    #pragma unroll
    for (int i = 0; i < 8; i++) {
        int slot = i * 256 + tid;
        int r = slot >> 5;
        int c4 = slot & 31;
        int gr = row0 + r;
        float4 va = make_float4(0.f, 0.f, 0.f, 0.f);
        if (gr < N) va = *((const float4*)A + gr * 32 + c4);
        *(float4*)(As + r * ASTRIDE + c4 * 4) = va;
        if (hasB) {
            float4 vb = make_float4(0.f, 0.f, 0.f, 0.f);
            if (gr < N) vb = *((const float4*)B + gr * 32 + c4);
            *(float4*)(Bs + r * ASTRIDE + c4 * 4) = vb;
        }
    }
    __syncthreads();

    const int cq = tid & 15;     // 16 col-threads, 8 cols each: c0 = cq*8
    const int rg = tid >> 4;     // 16 row-threads, rows rg + 16*i
    const ulonglong2* W1v = (const ulonglong2*)W1;   // 32 x 16B per 128-float row
    const ulonglong2* W2v = (const ulonglong2*)W2;

    u64 acc[4][4];
    #pragma unroll
    for (int i = 0; i < 4; i++)
        #pragma unroll
        for (int p = 0; p < 4; p++) acc[i][p] = 0ULL;

    if (hasB) {
        #pragma unroll 2
        for (int k = 0; k < 128; k++) {
            ulonglong2 w10 = W1v[k * 32 + cq * 2];
            ulonglong2 w11 = W1v[k * 32 + cq * 2 + 1];
            ulonglong2 w20 = W2v[k * 32 + cq * 2];
            ulonglong2 w21 = W2v[k * 32 + cq * 2 + 1];
            #pragma unroll
            for (int i = 0; i < 4; i++) {
                u64 aa = f2pack(As[(rg + i * 16) * ASTRIDE + k]);
                acc[i][0] = f2fma(aa, w10.x, acc[i][0]);
                acc[i][1] = f2fma(aa, w10.y, acc[i][1]);
                acc[i][2] = f2fma(aa, w11.x, acc[i][2]);
                acc[i][3] = f2fma(aa, w11.y, acc[i][3]);
                u64 bb = f2pack(Bs[(rg + i * 16) * ASTRIDE + k]);
                acc[i][0] = f2fma(bb, w20.x, acc[i][0]);
                acc[i][1] = f2fma(bb, w20.y, acc[i][1]);
                acc[i][2] = f2fma(bb, w21.x, acc[i][2]);
                acc[i][3] = f2fma(bb, w21.y, acc[i][3]);
            }
        }
    } else {
        #pragma unroll 2
        for (int k = 0; k < 128; k++) {
            ulonglong2 w10 = W1v[k * 32 + cq * 2];
            ulonglong2 w11 = W1v[k * 32 + cq * 2 + 1];
            #pragma unroll
            for (int i = 0; i < 4; i++) {
                u64 aa = f2pack(As[(rg + i * 16) * ASTRIDE + k]);
                acc[i][0] = f2fma(aa, w10.x, acc[i][0]);
                acc[i][1] = f2fma(aa, w10.y, acc[i][1]);
                acc[i][2] = f2fma(aa, w11.x, acc[i][2]);
                acc[i][3] = f2fma(aa, w11.y, acc[i][3]);
            }
        }
    }

    // epilogue
    const int c0 = cq * 8;
    float ob[8] = {0,0,0,0,0,0,0,0};
    if (bias) {
        float4 b0 = *((const float4*)(bias + c0));
        float4 b1 = *((const float4*)(bias + c0 + 4));
        ob[0]=b0.x; ob[1]=b0.y; ob[2]=b0.z; ob[3]=b0.w;
        ob[4]=b1.x; ob[5]=b1.y; ob[6]=b1.z; ob[7]=b1.w;
    }
    #pragma unroll
    for (int i = 0; i < 4; i++) {
        int gr = row0 + rg + i * 16;
        if (gr >= N) continue;
        float o[8];
        f2unpack(acc[i][0], o[0], o[1]);
        f2unpack(acc[i][1], o[2], o[3]);
        f2unpack(acc[i][2], o[4], o[5]);
        f2unpack(acc[i][3], o[6], o[7]);
        #pragma unroll
        for (int j = 0; j < 8; j++) o[j] += ob[j];
        if (resid) {
            float4 r0 = *((const float4*)(resid + gr * HD + c0));
            float4 r1 = *((const float4*)(resid + gr * HD + c0 + 4));
            o[0]+=r0.x; o[1]+=r0.y; o[2]+=r0.z; o[3]+=r0.w;
            o[4]+=r1.x; o[5]+=r1.y; o[6]+=r1.z; o[7]+=r1.w;
        }
        if (doRelu) {
            #pragma unroll
            for (int j = 0; j < 8; j++) o[j] = fmaxf(o[j], 0.f);
        }
        *(float4*)(C + gr * HD + c0)     = make_float4(o[0], o[1], o[2], o[3]);
        *(float4*)(C + gr * HD + c0 + 4) = make_float4(o[4], o[5], o[6], o[7]);
    }
}

// ---------------- context gather: enr[u] += sum pcW[dst] + sum urlW[dst] ----------------
__global__ void ctx_gather_kernel(const float* __restrict__ pcW, const float* __restrict__ urlW,
                                  const int* __restrict__ offP, const int* __restrict__ adjP,
                                  const int* __restrict__ offR, const int* __restrict__ adjR,
                                  float* __restrict__ enr) {
    int u = blockIdx.x, t = threadIdx.x;   // 128 threads
    float acc = enr[u * HD + t];
    {
        int beg = offP[u], end = offP[u + 1];
        int e = beg;
        for (; e + 2 <= end; e += 2) {
            int i0 = adjP[e], i1 = adjP[e + 1];
            acc += pcW[i0 * HD + t] + pcW[i1 * HD + t];
        }
        for (; e < end; e++) acc += pcW[adjP[e] * HD + t];
    }
    {
        int beg = offR[u], end = offR[u + 1];
        int e = beg;
        for (; e + 2 <= end; e += 2) {
            int i0 = adjR[e], i1 = adjR[e + 1];
            acc += urlW[i0 * HD + t] + urlW[i1 * HD + t];
        }
        for (; e < end; e++) acc += urlW[adjR[e] * HD + t];
    }
    enr[u * HD + t] = acc;
}

// ---------------- fused classifier: out = relu(enr@Wc1+bc1)@Wc2 + bc2 ----------------
__global__ void __launch_bounds__(256) classifier_kernel(
    const float* __restrict__ enr, const float* __restrict__ Wc1, const float* __restrict__ bc1,
    const float* __restrict__ Wc2, const float* __restrict__ bc2,
    float* __restrict__ out, int N)
{
    __shared__ float sW1[HD * 64];
    __shared__ float sW2[64 * 2];
    __shared__ float sb1[64];
    __shared__ float sb2[2];
    __shared__ __align__(16) float se[8][HD];
    int tid = threadIdx.x;
    for (int i = tid; i < HD * 64; i += 256) sW1[i] = Wc1[i];
    for (int i = tid; i < 128; i += 256) sW2[i] = Wc2[i];
    if (tid < 64) sb1[tid] = bc1[tid];
    if (tid < 2) sb2[tid] = bc2[tid];
    __syncthreads();
    int warp = tid >> 5, lane = tid & 31;
    int row = blockIdx.x * 8 + warp;
    if (row < N) {
        float4 v = *((const float4*)enr + row * 32 + lane);
        ((float4*)&se[warp][0])[lane] = v;
    }
    __syncwarp();
    if (row < N) {
        float h0 = sb1[lane], h1 = sb1[lane + 32];
        #pragma unroll 8
        for (int k = 0; k < HD; k++) {
            float e = se[warp][k];
            h0 = fmaf(e, sW1[k * 64 + lane], h0);
            h1 = fmaf(e, sW1[k * 64 + lane + 32], h1);
        }
        h0 = fmaxf(h0, 0.f); h1 = fmaxf(h1, 0.f);
        float p0 = h0 * sW2[lane * 2 + 0] + h1 * sW2[(lane + 32) * 2 + 0];
        float p1 = h0 * sW2[lane * 2 + 1] + h1 * sW2[(lane + 32) * 2 + 1];
        #pragma unroll
        for (int o = 16; o > 0; o >>= 1) {
            p0 += __shfl_down_sync(0xffffffff, p0, o);
            p1 += __shfl_down_sync(0xffffffff, p1, o);
        }
        if (lane == 0) {
            out[row * 2 + 0] = p0 + sb2[0];
            out[row * 2 + 1] = p1 + sb2[1];
        }
    }
}

// ---------------- host orchestration ----------------
#define SYMADDR(p, s) do { void* _t; cudaGetSymbolAddress(&_t, s); p = (decltype(p))_t; } while (0)

extern "C" void kernel_launch(void* const* d_in, const int* in_sizes, int n_in,
                              void* d_out, int out_size) {
    const float* x_user = (const float*)d_in[0];
    const float* x_pc   = (const float*)d_in[1];
    const float* x_url  = (const float*)d_in[2];
    const int* up_src   = (const int*)d_in[3];
    const int* up_dst   = (const int*)d_in[4];
    const int* uu_src   = (const int*)d_in[5];
    const int* uu_dst   = (const int*)d_in[6];
    const float* Wu = (const float*)d_in[7];
    const float* bu = (const float*)d_in[8];
    const float* Wp = (const float*)d_in[9];
    const float* bp = (const float*)d_in[10];
    const float* Wrf = (const float*)d_in[11];
    const float* brf = (const float*)d_in[12];
    const float* Wl_pc = (const float*)d_in[13];
    const float* bl_pc = (const float*)d_in[14];
    const float* Wr_pc = (const float*)d_in[15];
    const float* Wl_url = (const float*)d_in[16];
    const float* bl_url = (const float*)d_in[17];
    const float* Wr_url = (const float*)d_in[18];
    const float* Wctx = (const float*)d_in[19];
    const float* bctx = (const float*)d_in[20];
    const float* Wc1 = (const float*)d_in[21];
    const float* bc1 = (const float*)d_in[22];
    const float* Wc2 = (const float*)d_in[23];
    const float* bc2 = (const float*)d_in[24];
    float* out = (float*)d_out;

    float *user, *pc_a, *pc_b, *url_a, *url_b, *mean_pc, *mean_url, *pcW, *urlW, *enr;
    SYMADDR(user, g_user); SYMADDR(pc_a, g_pc_a); SYMADDR(pc_b, g_pc_b);
    SYMADDR(url_a, g_url_a); SYMADDR(url_b, g_url_b);
    SYMADDR(mean_pc, g_mean_pc); SYMADDR(mean_url, g_mean_url);
    SYMADDR(pcW, g_pcW); SYMADDR(urlW, g_urlW); SYMADDR(enr, g_enr);

    int *cnt_upd, *off_upd, *cur_upd, *adj_upd;
    int *cnt_uud, *off_uud, *cur_uud, *adj_uud;
    int *cnt_ups, *off_ups, *cur_ups, *adj_ups;
    int *cnt_uus, *off_uus, *cur_uus, *adj_uus;
    SYMADDR(cnt_upd, g_cnt_upd); SYMADDR(off_upd, g_off_upd); SYMADDR(cur_upd, g_cur_upd); SYMADDR(adj_upd, g_adj_upd);
    SYMADDR(cnt_uud, g_cnt_uud); SYMADDR(off_uud, g_off_uud); SYMADDR(cur_uud, g_cur_uud); SYMADDR(adj_uud, g_adj_uud);
    SYMADDR(cnt_ups, g_cnt_ups); SYMADDR(off_ups, g_off_ups); SYMADDR(cur_ups, g_cur_ups); SYMADDR(adj_ups, g_adj_ups);
    SYMADDR(cnt_uus, g_cnt_uus); SYMADDR(off_uus, g_off_uus); SYMADDR(cur_uus, g_cur_uus); SYMADDR(adj_uus, g_adj_uus);

    const int SM2 = 2 * 64 * ASTRIDE * 4;   // dual-matrix tile smem
    const int SM1 = 64 * ASTRIDE * 4;       // single-matrix tile smem
    cudaFuncSetAttribute(gemm128, cudaFuncAttributeMaxDynamicSharedMemorySize, SM2);

    // ---- CSR build ----
    zero4_kernel<<<(NU + 255) / 256, 256>>>(cnt_upd, NPC, cnt_uud, NURL, cnt_ups, NU, cnt_uus, NU);
    count_kernel<<<(EUP + 255) / 256, 256>>>(up_src, up_dst, EUP, cnt_ups, cnt_upd);
    count_kernel<<<(EUU + 255) / 256, 256>>>(uu_src, uu_dst, EUU, cnt_uus, cnt_uud);
    ScanSet s0{cnt_upd, off_upd, cur_upd, NPC};
    ScanSet s1{cnt_uud, off_uud, cur_uud, NURL};
    ScanSet s2{cnt_ups, off_ups, cur_ups, NU};
    ScanSet s3{cnt_uus, off_uus, cur_uus, NU};
    scan4_kernel<<<4, 1024>>>(s0, s1, s2, s3);
    fill_kernel<<<(EUP + 255) / 256, 256>>>(up_src, up_dst, EUP, cur_ups, adj_ups, cur_upd, adj_upd);
    fill_kernel<<<(EUU + 255) / 256, 256>>>(uu_src, uu_dst, EUU, cur_uus, adj_uus, cur_uud, adj_uud);

    // ---- input projections ----
    proj_kernel<<<(NU + 31) / 32, 128>>>(x_user, Wu, bu, user, NU, 6);
    proj_kernel<<<(NPC + 31) / 32, 128>>>(x_pc, Wp, bp, pc_a, NPC, 4);
    proj_kernel<<<(NURL + 31) / 32, 128>>>(x_url, Wrf, brf, url_a, NURL, 3);

    // ---- mean aggregation (same for both layers: user is never updated) ----
    agg_mean_kernel<<<NPC, 128>>>(user, off_upd, adj_upd, mean_pc);
    agg_mean_kernel<<<NURL, 128>>>(user, off_uud, adj_uud, mean_url);

    // ---- SAGE layers as fused GEMMs ----
    gemm128<<<(NPC + 63) / 64, 256, SM2>>>(mean_pc, Wl_pc, pc_a, Wr_pc, bl_pc, nullptr, pc_b, NPC, 1);
    gemm128<<<(NURL + 63) / 64, 256, SM2>>>(mean_url, Wl_url, url_a, Wr_url, bl_url, nullptr, url_b, NURL, 1);
    gemm128<<<(NPC + 63) / 64, 256, SM2>>>(mean_pc, Wl_pc + HD * HD, pc_b, Wr_pc + HD * HD,
                                           bl_pc + HD, pc_b, pc_a, NPC, 1);
    gemm128<<<(NURL + 63) / 64, 256, SM2>>>(mean_url, Wl_url + HD * HD, url_b, Wr_url + HD * HD,
                                            bl_url + HD, url_b, url_a, NURL, 1);

    // ---- context: project resources FIRST (linearity), then gather into users ----
    gemm128<<<(NPC + 63) / 64, 256, SM1>>>(pc_a, Wctx + HD * HD, nullptr, nullptr, nullptr, nullptr, pcW, NPC, 0);
    gemm128<<<(NURL + 63) / 64, 256, SM1>>>(url_a, Wctx + 2 * HD * HD, nullptr, nullptr, nullptr, nullptr, urlW, NURL, 0);
    gemm128<<<(NU + 63) / 64, 256, SM1>>>(user, Wctx, nullptr, nullptr, bctx, nullptr, enr, NU, 0);
    ctx_gather_kernel<<<NU, 128>>>(pcW, urlW, off_ups, adj_ups, off_uus, adj_uus, enr);

    // ---- fused classifier ----
    classifier_kernel<<<(NU + 7) / 8, 256>>>(enr, Wc1, bc1, Wc2, bc2, out, NU);
}

// round 3
// speedup vs baseline: 1.3610x; 1.3610x over previous
#include <cuda_runtime.h>
#include <cstdint>

#define NU   100000
#define NPC  20000
#define NURL 50000
#define EUP  250000
#define EUU  500000
#define HD   128
#define MAXB 128   // max scan blocks per set (NU/1024 = 98)

// ---------------- scratch (static __device__, 16B-aligned for float4 access) ----------------
__device__ __align__(16) float g_user[NU*HD];
__device__ __align__(16) float g_pc_a[NPC*HD];
__device__ __align__(16) float g_pc_b[NPC*HD];
__device__ __align__(16) float g_url_a[NURL*HD];
__device__ __align__(16) float g_url_b[NURL*HD];
__device__ __align__(16) float g_mean_pc[NPC*HD];
__device__ __align__(16) float g_mean_url[NURL*HD];
__device__ __align__(16) float g_pcW[NPC*HD];
__device__ __align__(16) float g_urlW[NURL*HD];
__device__ __align__(16) float g_enr[NU*HD];

__device__ __align__(16) int g_cnt_upd[NPC];  __device__ int g_off_upd[NPC+1];  __device__ int g_cur_upd[NPC];  __device__ int g_adj_upd[EUP];
__device__ __align__(16) int g_cnt_uud[NURL]; __device__ int g_off_uud[NURL+1]; __device__ int g_cur_uud[NURL]; __device__ int g_adj_uud[EUU];
__device__ __align__(16) int g_cnt_ups[NU];   __device__ int g_off_ups[NU+1];   __device__ int g_cur_ups[NU];   __device__ int g_adj_ups[EUP];
__device__ __align__(16) int g_cnt_uus[NU];   __device__ int g_off_uus[NU+1];   __device__ int g_cur_uus[NU];   __device__ int g_adj_uus[EUU];
__device__ int g_part[4*MAXB];

// ---------------- f32x2 packed-FMA helpers ----------------
typedef unsigned long long u64;
__device__ __forceinline__ u64 f2fma(u64 a, u64 b, u64 c) {
    u64 d; asm("fma.rn.f32x2 %0, %1, %2, %3;" : "=l"(d) : "l"(a), "l"(b), "l"(c)); return d;
}
__device__ __forceinline__ u64 f2pack(float x) {
    u64 r; asm("mov.b64 %0, {%1, %1};" : "=l"(r) : "f"(x)); return r;
}
__device__ __forceinline__ void f2unpack(u64 v, float& x, float& y) {
    asm("mov.b64 {%0, %1}, %2;" : "=f"(x), "=f"(y) : "l"(v));
}

// ---------------- CSR build ----------------
__global__ void zero4_kernel(int* a, int na, int* b, int nb, int* c, int nc, int* d, int nd) {
    int i = blockIdx.x * blockDim.x + threadIdx.x;
    if (i < na) a[i] = 0;
    if (i < nb) b[i] = 0;
    if (i < nc) c[i] = 0;
    if (i < nd) d[i] = 0;
}

__global__ void count_kernel(const int* __restrict__ src, const int* __restrict__ dst, int E,
                             int* cntS, int* cntD) {
    int i = blockIdx.x * blockDim.x + threadIdx.x;
    if (i < E) {
        atomicAdd(&cntD[dst[i]], 1);
        atomicAdd(&cntS[src[i]], 1);
    }
}

struct SetDesc { const int* cnt; int* off; int* cur; int n; };

__device__ __forceinline__ SetDesc pick_set(int sel, SetDesc s0, SetDesc s1, SetDesc s2, SetDesc s3) {
    if (sel == 1) return s1;
    if (sel == 2) return s2;
    if (sel == 3) return s3;
    return s0;
}

// Phase A: per-block (1024 elems) reduction -> g_part
__global__ void scanA_kernel(SetDesc s0, SetDesc s1, SetDesc s2, SetDesc s3) {
    SetDesc s = pick_set(blockIdx.y, s0, s1, s2, s3);
    int nb = (s.n + 1023) >> 10;
    if ((int)blockIdx.x >= nb) return;
    int tid = threadIdx.x;                          // 256 threads
    int i = blockIdx.x * 1024 + tid * 4;
    int sum = 0;
    #pragma unroll
    for (int j = 0; j < 4; j++) { int idx = i + j; if (idx < s.n) sum += s.cnt[idx]; }
    #pragma unroll
    for (int o = 16; o > 0; o >>= 1) sum += __shfl_down_sync(0xffffffffu, sum, o);
    __shared__ int ws[8];
    if ((tid & 31) == 0) ws[tid >> 5] = sum;
    __syncthreads();
    if (tid < 8) {
        int v = ws[tid];
        #pragma unroll
        for (int o = 4; o > 0; o >>= 1) v += __shfl_down_sync(0xffu, v, o);
        if (tid == 0) g_part[blockIdx.y * MAXB + blockIdx.x] = v;
    }
}

// Phase B: exclusive-scan the <=128 block partials per set; write off[n]=total
__global__ void scanB_kernel(SetDesc s0, SetDesc s1, SetDesc s2, SetDesc s3) {
    SetDesc s = pick_set(blockIdx.x, s0, s1, s2, s3);
    int nb = (s.n + 1023) >> 10;
    int tid = threadIdx.x;                          // 128 threads
    int v = (tid < nb) ? g_part[blockIdx.x * MAXB + tid] : 0;
    int lane = tid & 31, w = tid >> 5;
    int x = v;
    #pragma unroll
    for (int o = 1; o < 32; o <<= 1) { int y = __shfl_up_sync(0xffffffffu, x, o); if (lane >= o) x += y; }
    __shared__ int wt[4];
    if (lane == 31) wt[w] = x;
    __syncthreads();
    int add = 0;
    for (int j = 0; j < w; j++) add += wt[j];
    int incl = x + add;
    if (tid < nb) g_part[blockIdx.x * MAXB + tid] = incl - v;   // exclusive
    if (tid == 127) s.off[s.n] = incl;                          // grand total
}

// Phase C: local exclusive scan + block base -> off/cur
__global__ void scanC_kernel(SetDesc s0, SetDesc s1, SetDesc s2, SetDesc s3) {
    SetDesc s = pick_set(blockIdx.y, s0, s1, s2, s3);
    int nb = (s.n + 1023) >> 10;
    if ((int)blockIdx.x >= nb) return;
    int tid = threadIdx.x;                          // 256 threads
    int base = g_part[blockIdx.y * MAXB + blockIdx.x];
    int i = blockIdx.x * 1024 + tid * 4;
    int v0 = 0, v1 = 0, v2 = 0, v3 = 0;
    if (i     < s.n) v0 = s.cnt[i];
    if (i + 1 < s.n) v1 = s.cnt[i + 1];
    if (i + 2 < s.n) v2 = s.cnt[i + 2];
    if (i + 3 < s.n) v3 = s.cnt[i + 3];
    int sv = v0 + v1 + v2 + v3;
    int lane = tid & 31, w = tid >> 5;
    int x = sv;
    #pragma unroll
    for (int o = 1; o < 32; o <<= 1) { int y = __shfl_up_sync(0xffffffffu, x, o); if (lane >= o) x += y; }
    __shared__ int wt[8];
    if (lane == 31) wt[w] = x;
    __syncthreads();
    int add = base;
    for (int j = 0; j < w; j++) add += wt[j];
    int e0 = add + x - sv;
    int e1 = e0 + v0, e2 = e1 + v1, e3 = e2 + v2;
    if (i     < s.n) { s.off[i]     = e0; s.cur[i]     = e0; }
    if (i + 1 < s.n) { s.off[i + 1] = e1; s.cur[i + 1] = e1; }
    if (i + 2 < s.n) { s.off[i + 2] = e2; s.cur[i + 2] = e2; }
    if (i + 3 < s.n) { s.off[i + 3] = e3; s.cur[i + 3] = e3; }
}

__global__ void fill_kernel(const int* __restrict__ src, const int* __restrict__ dst, int E,
                            int* curS, int* adjS, int* curD, int* adjD) {
    int i = blockIdx.x * blockDim.x + threadIdx.x;
    if (i < E) {
        int svv = src[i], dvv = dst[i];
        adjD[atomicAdd(&curD[dvv], 1)] = svv;
        adjS[atomicAdd(&curS[svv], 1)] = dvv;
    }
}

// ---------------- small-K input projection: out[N,128] = X[N,Kin] @ W + b ----------------
__global__ void proj_kernel(const float* __restrict__ X, const float* __restrict__ W,
                            const float* __restrict__ b, float* __restrict__ out,
                            int N, int Kin) {
    __shared__ float sW[8 * HD];
    __shared__ float sb[HD];
    __shared__ float sx[32 * 8];
    int tid = threadIdx.x;                 // 128 threads
    for (int i = tid; i < Kin * HD; i += 128) sW[i] = W[i];
    sb[tid] = b[tid];
    int row0 = blockIdx.x * 32;
    int total = 32 * Kin;
    for (int i = tid; i < total; i += 128) {
        int gr = row0 + i / Kin;
        sx[i] = (gr < N) ? X[row0 * Kin + i] : 0.f;
    }
    __syncthreads();
    #pragma unroll 4
    for (int r = 0; r < 32; r++) {
        int gr = row0 + r;
        if (gr >= N) break;
        float acc = sb[tid];
        for (int j = 0; j < Kin; j++) acc = fmaf(sx[r * Kin + j], sW[j * HD + tid], acc);
        out[gr * HD + tid] = acc;
    }
}

// ---------------- gather-based segment mean (CSR by dst) ----------------
__global__ void agg_mean_kernel(const float* __restrict__ feat, const int* __restrict__ off,
                                const int* __restrict__ adj, float* __restrict__ out) {
    int s = blockIdx.x, t = threadIdx.x;   // 128 threads
    int beg = off[s], end = off[s + 1];
    float acc = 0.f;
    int e = beg;
    for (; e + 4 <= end; e += 4) {
        int i0 = adj[e], i1 = adj[e + 1], i2 = adj[e + 2], i3 = adj[e + 3];
        float a0 = feat[i0 * HD + t], a1 = feat[i1 * HD + t];
        float a2 = feat[i2 * HD + t], a3 = feat[i3 * HD + t];
        acc += (a0 + a1) + (a2 + a3);
    }
    for (; e < end; e++) acc += feat[adj[e] * HD + t];
    float inv = (end > beg) ? 1.f / (float)(end - beg) : 0.f;
    out[s * HD + t] = acc * inv;
}

// ---------------- fused GEMM: C = act(A@W1 [+ B@W2] [+bias] [+resid]) , K=128, 128 cols ----------------
#define ASTRIDE 132
__global__ void __launch_bounds__(256, 2) gemm128(
    const float* __restrict__ A, const float* __restrict__ W1,
    const float* __restrict__ B, const float* __restrict__ W2,
    const float* __restrict__ bias, const float* __restrict__ resid,
    float* __restrict__ C, int N, int doRelu)
{
    extern __shared__ float smem[];
    float* As = smem;
    float* Bs = smem + 64 * ASTRIDE;
    const int tid = threadIdx.x;
    const int row0 = blockIdx.x * 64;
    const bool hasB = (B != nullptr);

    // load 64x128 tiles (padded rows -> conflict-free column reads)
    #pragma unroll
    for (int i = 0; i < 8; i++) {
        int slot = i * 256 + tid;
        int r = slot >> 5;
        int c4 = slot & 31;
        int gr = row0 + r;
        float4 va = make_float4(0.f, 0.f, 0.f, 0.f);
        if (gr < N) va = *((const float4*)A + gr * 32 + c4);
        *(float4*)(As + r * ASTRIDE + c4 * 4) = va;
        if (hasB) {
            float4 vb = make_float4(0.f, 0.f, 0.f, 0.f);
            if (gr < N) vb = *((const float4*)B + gr * 32 + c4);
            *(float4*)(Bs + r * ASTRIDE + c4 * 4) = vb;
        }
    }
    __syncthreads();

    const int cq = tid & 15;     // 16 col-threads, 8 cols each: c0 = cq*8
    const int rg = tid >> 4;     // 16 row-threads, rows rg + 16*i
    const ulonglong2* W1v = (const ulonglong2*)W1;   // 32 x 16B per 128-float row
    const ulonglong2* W2v = (const ulonglong2*)W2;

    u64 acc[4][4];
    #pragma unroll
    for (int i = 0; i < 4; i++)
        #pragma unroll
        for (int p = 0; p < 4; p++) acc[i][p] = 0ULL;

    if (hasB) {
        #pragma unroll 1
        for (int k = 0; k < 128; k += 2) {
            ulonglong2 w10a = W1v[k * 32 + cq * 2];
            ulonglong2 w10b = W1v[k * 32 + cq * 2 + 1];
            ulonglong2 w11a = W1v[(k + 1) * 32 + cq * 2];
            ulonglong2 w11b = W1v[(k + 1) * 32 + cq * 2 + 1];
            ulonglong2 w20a = W2v[k * 32 + cq * 2];
            ulonglong2 w20b = W2v[k * 32 + cq * 2 + 1];
            ulonglong2 w21a = W2v[(k + 1) * 32 + cq * 2];
            ulonglong2 w21b = W2v[(k + 1) * 32 + cq * 2 + 1];
            #pragma unroll
            for (int i = 0; i < 4; i++) {
                float2 a2 = *(const float2*)&As[(rg + i * 16) * ASTRIDE + k];
                u64 aa0 = f2pack(a2.x), aa1 = f2pack(a2.y);
                acc[i][0] = f2fma(aa0, w10a.x, acc[i][0]);
                acc[i][1] = f2fma(aa0, w10a.y, acc[i][1]);
                acc[i][2] = f2fma(aa0, w10b.x, acc[i][2]);
                acc[i][3] = f2fma(aa0, w10b.y, acc[i][3]);
                acc[i][0] = f2fma(aa1, w11a.x, acc[i][0]);
                acc[i][1] = f2fma(aa1, w11a.y, acc[i][1]);
                acc[i][2] = f2fma(aa1, w11b.x, acc[i][2]);
                acc[i][3] = f2fma(aa1, w11b.y, acc[i][3]);
                float2 b2 = *(const float2*)&Bs[(rg + i * 16) * ASTRIDE + k];
                u64 bb0 = f2pack(b2.x), bb1 = f2pack(b2.y);
                acc[i][0] = f2fma(bb0, w20a.x, acc[i][0]);
                acc[i][1] = f2fma(bb0, w20a.y, acc[i][1]);
                acc[i][2] = f2fma(bb0, w20b.x, acc[i][2]);
                acc[i][3] = f2fma(bb0, w20b.y, acc[i][3]);
                acc[i][0] = f2fma(bb1, w21a.x, acc[i][0]);
                acc[i][1] = f2fma(bb1, w21a.y, acc[i][1]);
                acc[i][2] = f2fma(bb1, w21b.x, acc[i][2]);
                acc[i][3] = f2fma(bb1, w21b.y, acc[i][3]);
            }
        }
    } else {
        #pragma unroll 1
        for (int k = 0; k < 128; k += 2) {
            ulonglong2 w10a = W1v[k * 32 + cq * 2];
            ulonglong2 w10b = W1v[k * 32 + cq * 2 + 1];
            ulonglong2 w11a = W1v[(k + 1) * 32 + cq * 2];
            ulonglong2 w11b = W1v[(k + 1) * 32 + cq * 2 + 1];
            #pragma unroll
            for (int i = 0; i < 4; i++) {
                float2 a2 = *(const float2*)&As[(rg + i * 16) * ASTRIDE + k];
                u64 aa0 = f2pack(a2.x), aa1 = f2pack(a2.y);
                acc[i][0] = f2fma(aa0, w10a.x, acc[i][0]);
                acc[i][1] = f2fma(aa0, w10a.y, acc[i][1]);
                acc[i][2] = f2fma(aa0, w10b.x, acc[i][2]);
                acc[i][3] = f2fma(aa0, w10b.y, acc[i][3]);
                acc[i][0] = f2fma(aa1, w11a.x, acc[i][0]);
                acc[i][1] = f2fma(aa1, w11a.y, acc[i][1]);
                acc[i][2] = f2fma(aa1, w11b.x, acc[i][2]);
                acc[i][3] = f2fma(aa1, w11b.y, acc[i][3]);
            }
        }
    }

    // epilogue
    const int c0 = cq * 8;
    float ob[8] = {0,0,0,0,0,0,0,0};
    if (bias) {
        float4 b0 = *((const float4*)(bias + c0));
        float4 b1 = *((const float4*)(bias + c0 + 4));
        ob[0]=b0.x; ob[1]=b0.y; ob[2]=b0.z; ob[3]=b0.w;
        ob[4]=b1.x; ob[5]=b1.y; ob[6]=b1.z; ob[7]=b1.w;
    }
    #pragma unroll
    for (int i = 0; i < 4; i++) {
        int gr = row0 + rg + i * 16;
        if (gr >= N) continue;
        float o[8];
        f2unpack(acc[i][0], o[0], o[1]);
        f2unpack(acc[i][1], o[2], o[3]);
        f2unpack(acc[i][2], o[4], o[5]);
        f2unpack(acc[i][3], o[6], o[7]);
        #pragma unroll
        for (int j = 0; j < 8; j++) o[j] += ob[j];
        if (resid) {
            float4 r0 = *((const float4*)(resid + gr * HD + c0));
            float4 r1 = *((const float4*)(resid + gr * HD + c0 + 4));
            o[0]+=r0.x; o[1]+=r0.y; o[2]+=r0.z; o[3]+=r0.w;
            o[4]+=r1.x; o[5]+=r1.y; o[6]+=r1.z; o[7]+=r1.w;
        }
        if (doRelu) {
            #pragma unroll
            for (int j = 0; j < 8; j++) o[j] = fmaxf(o[j], 0.f);
        }
        *(float4*)(C + gr * HD + c0)     = make_float4(o[0], o[1], o[2], o[3]);
        *(float4*)(C + gr * HD + c0 + 4) = make_float4(o[4], o[5], o[6], o[7]);
    }
}

// ---------------- context gather: enr[u] += sum pcW[dst] + sum urlW[dst] ----------------
__global__ void ctx_gather_kernel(const float* __restrict__ pcW, const float* __restrict__ urlW,
                                  const int* __restrict__ offP, const int* __restrict__ adjP,
                                  const int* __restrict__ offR, const int* __restrict__ adjR,
                                  float* __restrict__ enr) {
    int u = blockIdx.x, t = threadIdx.x;   // 128 threads
    float acc = enr[u * HD + t];
    {
        int beg = offP[u], end = offP[u + 1];
        int e = beg;
        for (; e + 2 <= end; e += 2) {
            int i0 = adjP[e], i1 = adjP[e + 1];
            acc += pcW[i0 * HD + t] + pcW[i1 * HD + t];
        }
        for (; e < end; e++) acc += pcW[adjP[e] * HD + t];
    }
    {
        int beg = offR[u], end = offR[u + 1];
        int e = beg;
        for (; e + 2 <= end; e += 2) {
            int i0 = adjR[e], i1 = adjR[e + 1];
            acc += urlW[i0 * HD + t] + urlW[i1 * HD + t];
        }
        for (; e < end; e++) acc += urlW[adjR[e] * HD + t];
    }
    enr[u * HD + t] = acc;
}

// ---------------- fused classifier: out = relu(enr@Wc1+bc1)@Wc2 + bc2 ----------------
__global__ void __launch_bounds__(256) classifier_kernel(
    const float* __restrict__ enr, const float* __restrict__ Wc1, const float* __restrict__ bc1,
    const float* __restrict__ Wc2, const float* __restrict__ bc2,
    float* __restrict__ out, int N)
{
    __shared__ float sW1[HD * 64];
    __shared__ float sW2[64 * 2];
    __shared__ float sb1[64];
    __shared__ float sb2[2];
    __shared__ __align__(16) float se[8][HD];
    int tid = threadIdx.x;
    for (int i = tid; i < HD * 64; i += 256) sW1[i] = Wc1[i];
    for (int i = tid; i < 128; i += 256) sW2[i] = Wc2[i];
    if (tid < 64) sb1[tid] = bc1[tid];
    if (tid < 2) sb2[tid] = bc2[tid];
    __syncthreads();
    int warp = tid >> 5, lane = tid & 31;
    int row = blockIdx.x * 8 + warp;
    if (row < N) {
        float4 v = *((const float4*)enr + row * 32 + lane);
        ((float4*)&se[warp][0])[lane] = v;
    }
    __syncwarp();
    if (row < N) {
        float h0 = sb1[lane], h1 = sb1[lane + 32];
        #pragma unroll 8
        for (int k = 0; k < HD; k++) {
            float e = se[warp][k];
            h0 = fmaf(e, sW1[k * 64 + lane], h0);
            h1 = fmaf(e, sW1[k * 64 + lane + 32], h1);
        }
        h0 = fmaxf(h0, 0.f); h1 = fmaxf(h1, 0.f);
        float p0 = h0 * sW2[lane * 2 + 0] + h1 * sW2[(lane + 32) * 2 + 0];
        float p1 = h0 * sW2[lane * 2 + 1] + h1 * sW2[(lane + 32) * 2 + 1];
        #pragma unroll
        for (int o = 16; o > 0; o >>= 1) {
            p0 += __shfl_down_sync(0xffffffff, p0, o);
            p1 += __shfl_down_sync(0xffffffff, p1, o);
        }
        if (lane == 0) {
            out[row * 2 + 0] = p0 + sb2[0];
            out[row * 2 + 1] = p1 + sb2[1];
        }
    }
}

// ---------------- streams/events created at static init (baselined by harness checkpoints) ----------------
struct StreamCtx {
    cudaStream_t s1, s2, s3;
    cudaEvent_t evRoot, evCSRup, evCSRuu, evUser, evPC, evURL, evS3;
    StreamCtx() {
        cudaStreamCreateWithFlags(&s1, cudaStreamNonBlocking);
        cudaStreamCreateWithFlags(&s2, cudaStreamNonBlocking);
        cudaStreamCreateWithFlags(&s3, cudaStreamNonBlocking);
        cudaEventCreateWithFlags(&evRoot,  cudaEventDisableTiming);
        cudaEventCreateWithFlags(&evCSRup, cudaEventDisableTiming);
        cudaEventCreateWithFlags(&evCSRuu, cudaEventDisableTiming);
        cudaEventCreateWithFlags(&evUser,  cudaEventDisableTiming);
        cudaEventCreateWithFlags(&evPC,    cudaEventDisableTiming);
        cudaEventCreateWithFlags(&evURL,   cudaEventDisableTiming);
        cudaEventCreateWithFlags(&evS3,    cudaEventDisableTiming);
    }
};
static StreamCtx g_sc;

// ---------------- host orchestration ----------------
#define SYMADDR(p, s) do { void* _t; cudaGetSymbolAddress(&_t, s); p = (decltype(p))_t; } while (0)

extern "C" void kernel_launch(void* const* d_in, const int* in_sizes, int n_in,
                              void* d_out, int out_size) {
    const float* x_user = (const float*)d_in[0];
    const float* x_pc   = (const float*)d_in[1];
    const float* x_url  = (const float*)d_in[2];
    const int* up_src   = (const int*)d_in[3];
    const int* up_dst   = (const int*)d_in[4];
    const int* uu_src   = (const int*)d_in[5];
    const int* uu_dst   = (const int*)d_in[6];
    const float* Wu = (const float*)d_in[7];
    const float* bu = (const float*)d_in[8];
    const float* Wp = (const float*)d_in[9];
    const float* bp = (const float*)d_in[10];
    const float* Wrf = (const float*)d_in[11];
    const float* brf = (const float*)d_in[12];
    const float* Wl_pc = (const float*)d_in[13];
    const float* bl_pc = (const float*)d_in[14];
    const float* Wr_pc = (const float*)d_in[15];
    const float* Wl_url = (const float*)d_in[16];
    const float* bl_url = (const float*)d_in[17];
    const float* Wr_url = (const float*)d_in[18];
    const float* Wctx = (const float*)d_in[19];
    const float* bctx = (const float*)d_in[20];
    const float* Wc1 = (const float*)d_in[21];
    const float* bc1 = (const float*)d_in[22];
    const float* Wc2 = (const float*)d_in[23];
    const float* bc2 = (const float*)d_in[24];
    float* out = (float*)d_out;

    float *user, *pc_a, *pc_b, *url_a, *url_b, *mean_pc, *mean_url, *pcW, *urlW, *enr;
    SYMADDR(user, g_user); SYMADDR(pc_a, g_pc_a); SYMADDR(pc_b, g_pc_b);
    SYMADDR(url_a, g_url_a); SYMADDR(url_b, g_url_b);
    SYMADDR(mean_pc, g_mean_pc); SYMADDR(mean_url, g_mean_url);
    SYMADDR(pcW, g_pcW); SYMADDR(urlW, g_urlW); SYMADDR(enr, g_enr);

    int *cnt_upd, *off_upd, *cur_upd, *adj_upd;
    int *cnt_uud, *off_uud, *cur_uud, *adj_uud;
    int *cnt_ups, *off_ups, *cur_ups, *adj_ups;
    int *cnt_uus, *off_uus, *cur_uus, *adj_uus;
    SYMADDR(cnt_upd, g_cnt_upd); SYMADDR(off_upd, g_off_upd); SYMADDR(cur_upd, g_cur_upd); SYMADDR(adj_upd, g_adj_upd);
    SYMADDR(cnt_uud, g_cnt_uud); SYMADDR(off_uud, g_off_uud); SYMADDR(cur_uud, g_cur_uud); SYMADDR(adj_uud, g_adj_uud);
    SYMADDR(cnt_ups, g_cnt_ups); SYMADDR(off_ups, g_off_ups); SYMADDR(cur_ups, g_cur_ups); SYMADDR(adj_ups, g_adj_ups);
    SYMADDR(cnt_uus, g_cnt_uus); SYMADDR(off_uus, g_off_uus); SYMADDR(cur_uus, g_cur_uus); SYMADDR(adj_uus, g_adj_uus);

    const int SM2 = 2 * 64 * ASTRIDE * 4;
    const int SM1 = 64 * ASTRIDE * 4;
    cudaFuncSetAttribute(gemm128, cudaFuncAttributeMaxDynamicSharedMemorySize, SM2);

    cudaStream_t s0 = 0;
    cudaStream_t s1 = g_sc.s1, s2 = g_sc.s2, s3 = g_sc.s3;

    // ---- fork ----
    cudaEventRecord(g_sc.evRoot, s0);
    cudaStreamWaitEvent(s1, g_sc.evRoot, 0);
    cudaStreamWaitEvent(s2, g_sc.evRoot, 0);
    cudaStreamWaitEvent(s3, g_sc.evRoot, 0);

    // ---- s3: user projection, then enr GEMM (depends only on user) ----
    proj_kernel<<<(NU + 31) / 32, 128, 0, s3>>>(x_user, Wu, bu, user, NU, 6);
    cudaEventRecord(g_sc.evUser, s3);
    gemm128<<<(NU + 63) / 64, 256, SM1, s3>>>(user, Wctx, nullptr, nullptr, bctx, nullptr, enr, NU, 0);
    cudaEventRecord(g_sc.evS3, s3);

    // ---- s1/s2: pc/url input projections (independent of CSR) ----
    proj_kernel<<<(NPC + 31) / 32, 128, 0, s1>>>(x_pc, Wp, bp, pc_a, NPC, 4);
    proj_kernel<<<(NURL + 31) / 32, 128, 0, s2>>>(x_url, Wrf, brf, url_a, NURL, 3);

    // ---- s0: CSR build ----
    zero4_kernel<<<(NU + 255) / 256, 256, 0, s0>>>(cnt_upd, NPC, cnt_uud, NURL, cnt_ups, NU, cnt_uus, NU);
    count_kernel<<<(EUP + 255) / 256, 256, 0, s0>>>(up_src, up_dst, EUP, cnt_ups, cnt_upd);
    count_kernel<<<(EUU + 255) / 256, 256, 0, s0>>>(uu_src, uu_dst, EUU, cnt_uus, cnt_uud);
    SetDesc d0{cnt_upd, off_upd, cur_upd, NPC};
    SetDesc d1{cnt_uud, off_uud, cur_uud, NURL};
    SetDesc d2{cnt_ups, off_ups, cur_ups, NU};
    SetDesc d3{cnt_uus, off_uus, cur_uus, NU};
    dim3 gScan((NU + 1023) / 1024, 4);
    scanA_kernel<<<gScan, 256, 0, s0>>>(d0, d1, d2, d3);
    scanB_kernel<<<4, 128, 0, s0>>>(d0, d1, d2, d3);
    scanC_kernel<<<gScan, 256, 0, s0>>>(d0, d1, d2, d3);
    fill_kernel<<<(EUP + 255) / 256, 256, 0, s0>>>(up_src, up_dst, EUP, cur_ups, adj_ups, cur_upd, adj_upd);
    cudaEventRecord(g_sc.evCSRup, s0);
    fill_kernel<<<(EUU + 255) / 256, 256, 0, s0>>>(uu_src, uu_dst, EUU, cur_uus, adj_uus, cur_uud, adj_uud);
    cudaEventRecord(g_sc.evCSRuu, s0);

    // ---- s1: pc chain ----
    cudaStreamWaitEvent(s1, g_sc.evCSRup, 0);
    cudaStreamWaitEvent(s1, g_sc.evUser, 0);
    agg_mean_kernel<<<NPC, 128, 0, s1>>>(user, off_upd, adj_upd, mean_pc);
    gemm128<<<(NPC + 63) / 64, 256, SM2, s1>>>(mean_pc, Wl_pc, pc_a, Wr_pc, bl_pc, nullptr, pc_b, NPC, 1);
    gemm128<<<(NPC + 63) / 64, 256, SM2, s1>>>(mean_pc, Wl_pc + HD * HD, pc_b, Wr_pc + HD * HD,
                                               bl_pc + HD, pc_b, pc_a, NPC, 1);
    gemm128<<<(NPC + 63) / 64, 256, SM1, s1>>>(pc_a, Wctx + HD * HD, nullptr, nullptr, nullptr, nullptr, pcW, NPC, 0);
    cudaEventRecord(g_sc.evPC, s1);

    // ---- s2: url chain ----
    cudaStreamWaitEvent(s2, g_sc.evCSRuu, 0);
    cudaStreamWaitEvent(s2, g_sc.evUser, 0);
    agg_mean_kernel<<<NURL, 128, 0, s2>>>(user, off_uud, adj_uud, mean_url);
    gemm128<<<(NURL + 63) / 64, 256, SM2, s2>>>(mean_url, Wl_url, url_a, Wr_url, bl_url, nullptr, url_b, NURL, 1);
    gemm128<<<(NURL + 63) / 64, 256, SM2, s2>>>(mean_url, Wl_url + HD * HD, url_b, Wr_url + HD * HD,
                                                bl_url + HD, url_b, url_a, NURL, 1);
    gemm128<<<(NURL + 63) / 64, 256, SM1, s2>>>(url_a, Wctx + 2 * HD * HD, nullptr, nullptr, nullptr, nullptr, urlW, NURL, 0);
    cudaEventRecord(g_sc.evURL, s2);

    // ---- join on s0: context gather + classifier ----
    cudaStreamWaitEvent(s0, g_sc.evPC, 0);
    cudaStreamWaitEvent(s0, g_sc.evURL, 0);
    cudaStreamWaitEvent(s0, g_sc.evS3, 0);
    ctx_gather_kernel<<<NU, 128, 0, s0>>>(pcW, urlW, off_ups, adj_ups, off_uus, adj_uus, enr);
    classifier_kernel<<<(NU + 7) / 8, 256, 0, s0>>>(enr, Wc1, bc1, Wc2, bc2, out, NU);
}